// round 14
// baseline (speedup 1.0000x reference)
#include <cuda_runtime.h>
#include <cstdint>

typedef unsigned long long u64;

#define Bn   16
#define R    360
#define RPAD 384   // padded row length (float2 units) for u/v scratch

// Scratch: u2[b][dpair k][i] = (u[i][2k], u[i][2k+1]) packed fp32x2; same for v (v includes +b_out)
__device__ u64 g_u2[Bn * 32 * RPAD];
__device__ u64 g_v2[Bn * 32 * RPAD];

// ---------- packed fp32x2 helpers (sm_100+) ----------
__device__ __forceinline__ u64 pack2(float x, float y) {
    u64 d; asm("mov.b64 %0, {%1, %2};" : "=l"(d) : "f"(x), "f"(y)); return d;
}
__device__ __forceinline__ void unpack2(u64 a, float &x, float &y) {
    asm("mov.b64 {%0, %1}, %2;" : "=f"(x), "=f"(y) : "l"(a));
}
__device__ __forceinline__ void ffma2(u64 &d, u64 a, u64 b) {
    asm("fma.rn.f32x2 %0, %1, %2, %0;" : "+l"(d) : "l"(a), "l"(b));
}

// ============================================================================
// Kernel 1 (R10-proven): u = x @ Wout[0:64], v = x @ Wout[64:128] + b_out
// 360 blocks x 16 rows, 3 CTAs/SM.
// ============================================================================
__global__ __launch_bounds__(256, 3) void k1_uv(
    const float* __restrict__ x,      // [5760][64]
    const float* __restrict__ Wout,   // [128][64]
    const float* __restrict__ bout)   // [64]
{
    __shared__ u64 xs[16][33];
    __shared__ u64 Wu[32][64];
    __shared__ u64 Wv[32][64];

    const int t = threadIdx.x;
    const int row0 = blockIdx.x * 16;

    {
        const int c = t & 63, p0 = t >> 6;
        #pragma unroll
        for (int p = p0; p < 32; p += 4) {
            Wu[p][c] = pack2(Wout[(2 * p) * 64 + c],      Wout[(2 * p + 1) * 64 + c]);
            Wv[p][c] = pack2(Wout[(64 + 2 * p) * 64 + c], Wout[(65 + 2 * p) * 64 + c]);
        }
    }
    {
        const u64* x2 = (const u64*)x;
        #pragma unroll
        for (int idx = t; idx < 16 * 32; idx += 256) {
            const int r = idx >> 5, lane = idx & 31;
            xs[r][lane] = x2[(size_t)(row0 + r) * 32 + lane];
        }
    }
    __syncthreads();

    const int row  = t & 15;
    const int g    = t >> 4;
    const int ccol = (g & 7) * 8;
    const bool isv = (g >= 8);
    const u64 (*Ws)[64] = isv ? Wv : Wu;

    u64 acc[8];
    #pragma unroll
    for (int j = 0; j < 8; j++) acc[j] = 0ull;

    #pragma unroll
    for (int p = 0; p < 32; p++) {
        const u64 xv = xs[row][p];
        ulonglong2 wa = *(const ulonglong2*)&Ws[p][ccol];
        ulonglong2 wb = *(const ulonglong2*)&Ws[p][ccol + 2];
        ulonglong2 wc = *(const ulonglong2*)&Ws[p][ccol + 4];
        ulonglong2 wd = *(const ulonglong2*)&Ws[p][ccol + 6];
        ffma2(acc[0], xv, wa.x);  ffma2(acc[1], xv, wa.y);
        ffma2(acc[2], xv, wb.x);  ffma2(acc[3], xv, wb.y);
        ffma2(acc[4], xv, wc.x);  ffma2(acc[5], xv, wc.y);
        ffma2(acc[6], xv, wd.x);  ffma2(acc[7], xv, wd.y);
    }

    const int grow = row0 + row;
    const int bb = grow / 360;
    const int i = grow - bb * 360;
    u64* gdst = isv ? g_v2 : g_u2;
    #pragma unroll
    for (int j = 0; j < 8; j += 2) {
        float l0, h0, l1, h1;
        unpack2(acc[j],     l0, h0);
        unpack2(acc[j + 1], l1, h1);
        float v0 = l0 + h0, v1 = l1 + h1;
        const int dd = ccol + j;
        if (isv) { v0 += __ldg(&bout[dd]); v1 += __ldg(&bout[dd + 1]); }
        gdst[(bb * 32 + (dd >> 1)) * RPAD + i] = pack2(v0, v1);
    }
}

// One fused-asm k-step: all loads + 16 cells of (FADD2 + AND.b64(abs) + FFMA2),
// entirely inside PTX — no C++/asm boundary register marshaling.
#define K2_STEP(AU, AV, AW)                                                      \
    asm volatile("{\n\t"                                                         \
        ".reg .b64 w, u0, u1, v0, v1, v2, v3, v4, v5, v6, v7, s;\n\t"            \
        "ld.shared.b64 w, [%18];\n\t"                                            \
        "ld.shared.v2.b64 {u0, u1}, [%16];\n\t"                                  \
        "ld.shared.v2.b64 {v0, v1}, [%17];\n\t"                                  \
        "ld.shared.v2.b64 {v2, v3}, [%17+16];\n\t"                               \
        "ld.shared.v2.b64 {v4, v5}, [%17+32];\n\t"                               \
        "ld.shared.v2.b64 {v6, v7}, [%17+48];\n\t"                               \
        "add.rn.f32x2 s, u0, v0; and.b64 s, s, 0x7FFFFFFF7FFFFFFF; fma.rn.f32x2 %0, s, w, %0;\n\t"  \
        "add.rn.f32x2 s, u1, v0; and.b64 s, s, 0x7FFFFFFF7FFFFFFF; fma.rn.f32x2 %1, s, w, %1;\n\t"  \
        "add.rn.f32x2 s, u0, v1; and.b64 s, s, 0x7FFFFFFF7FFFFFFF; fma.rn.f32x2 %2, s, w, %2;\n\t"  \
        "add.rn.f32x2 s, u1, v1; and.b64 s, s, 0x7FFFFFFF7FFFFFFF; fma.rn.f32x2 %3, s, w, %3;\n\t"  \
        "add.rn.f32x2 s, u0, v2; and.b64 s, s, 0x7FFFFFFF7FFFFFFF; fma.rn.f32x2 %4, s, w, %4;\n\t"  \
        "add.rn.f32x2 s, u1, v2; and.b64 s, s, 0x7FFFFFFF7FFFFFFF; fma.rn.f32x2 %5, s, w, %5;\n\t"  \
        "add.rn.f32x2 s, u0, v3; and.b64 s, s, 0x7FFFFFFF7FFFFFFF; fma.rn.f32x2 %6, s, w, %6;\n\t"  \
        "add.rn.f32x2 s, u1, v3; and.b64 s, s, 0x7FFFFFFF7FFFFFFF; fma.rn.f32x2 %7, s, w, %7;\n\t"  \
        "add.rn.f32x2 s, u0, v4; and.b64 s, s, 0x7FFFFFFF7FFFFFFF; fma.rn.f32x2 %8, s, w, %8;\n\t"  \
        "add.rn.f32x2 s, u1, v4; and.b64 s, s, 0x7FFFFFFF7FFFFFFF; fma.rn.f32x2 %9, s, w, %9;\n\t"  \
        "add.rn.f32x2 s, u0, v5; and.b64 s, s, 0x7FFFFFFF7FFFFFFF; fma.rn.f32x2 %10, s, w, %10;\n\t" \
        "add.rn.f32x2 s, u1, v5; and.b64 s, s, 0x7FFFFFFF7FFFFFFF; fma.rn.f32x2 %11, s, w, %11;\n\t" \
        "add.rn.f32x2 s, u0, v6; and.b64 s, s, 0x7FFFFFFF7FFFFFFF; fma.rn.f32x2 %12, s, w, %12;\n\t" \
        "add.rn.f32x2 s, u1, v6; and.b64 s, s, 0x7FFFFFFF7FFFFFFF; fma.rn.f32x2 %13, s, w, %13;\n\t" \
        "add.rn.f32x2 s, u0, v7; and.b64 s, s, 0x7FFFFFFF7FFFFFFF; fma.rn.f32x2 %14, s, w, %14;\n\t" \
        "add.rn.f32x2 s, u1, v7; and.b64 s, s, 0x7FFFFFFF7FFFFFFF; fma.rn.f32x2 %15, s, w, %15;\n\t" \
        "}"                                                                      \
        : "+l"(a00), "+l"(a01), "+l"(a10), "+l"(a11),                            \
          "+l"(a20), "+l"(a21), "+l"(a30), "+l"(a31),                            \
          "+l"(a40), "+l"(a41), "+l"(a50), "+l"(a51),                            \
          "+l"(a60), "+l"(a61), "+l"(a70), "+l"(a71)                             \
        : "r"(AU), "r"(AV), "r"(AW))

// ============================================================================
// Kernel 2: out = relu( C_s + D_r + sum_d 0.5*w_d*|u_sd+v_rd| + b_cat )
// 64x64 tile, 2 sends x 8 recs/thread, fused-asm inner loop (zero marshaling).
// ============================================================================
__global__ __launch_bounds__(256, 4) void k2_pair(
    const float* __restrict__ Wcat,   // [64]
    const float* __restrict__ bcat,   // [1]
    float* __restrict__ out)          // [16*360*360]
{
    __shared__ u64 Us[32][64];    // [dpair][send]
    __shared__ u64 Vs[32][64];    // [dpair][rec]
    __shared__ u64 Ww[32];        // packed 0.5*Wcat pairs
    __shared__ float Cs[64];      // sum_d 0.5 w_d u_sd per send
    __shared__ float Ds[64];      // sum_d 0.5 w_d v_rd per rec

    const int t = threadIdx.x;
    const int b  = blockIdx.z;
    const int s0 = blockIdx.x * 64;
    const int r0 = blockIdx.y * 64;

    // Fill tiles (coalesced; pad region reads zeros)
    {
        const int c = t & 63, k0 = t >> 6;
        const u64* gu = g_u2 + b * 32 * RPAD + s0 + c;
        const u64* gv = g_v2 + b * 32 * RPAD + r0 + c;
        #pragma unroll
        for (int k = k0; k < 32; k += 4) {
            Us[k][c] = gu[k * RPAD];
            Vs[k][c] = gv[k * RPAD];
        }
        if (t < 32) {
            u64 w = ((const u64*)Wcat)[t];
            const u64 half2 = 0x3F0000003F000000ull;   // (0.5f, 0.5f)
            asm("mul.rn.f32x2 %0, %0, %1;" : "+l"(w) : "l"(half2));
            Ww[t] = w;
        }
    }
    __syncthreads();

    // Precompute C_s (warps 0-1) and D_r (warps 2-3)
    if (t < 128) {
        const int c = t & 63;
        const bool isD = (t >= 64);
        u64 a = 0ull;
        #pragma unroll 8
        for (int k = 0; k < 32; k++) {
            const u64 val = isD ? Vs[k][c] : Us[k][c];
            ffma2(a, val, Ww[k]);
        }
        float lo, hi; unpack2(a, lo, hi);
        if (isD) Ds[c] = lo + hi; else Cs[c] = lo + hi;
    }
    __syncthreads();

    const int lane = t & 31;       // sends 2*lane, 2*lane+1
    const int wg   = t >> 5;       // recs 8*wg .. 8*wg+7

    // 32-bit shared addresses for the fused-asm loads
    const unsigned au0 = (unsigned)__cvta_generic_to_shared(&Us[0][2 * lane]);
    const unsigned av0 = (unsigned)__cvta_generic_to_shared(&Vs[0][8 * wg]);
    const unsigned aw0 = (unsigned)__cvta_generic_to_shared(&Ww[0]);

    u64 a00 = 0, a01 = 0, a10 = 0, a11 = 0, a20 = 0, a21 = 0, a30 = 0, a31 = 0;
    u64 a40 = 0, a41 = 0, a50 = 0, a51 = 0, a60 = 0, a61 = 0, a70 = 0, a71 = 0;

    #pragma unroll 8
    for (int k = 0; k < 32; k++) {
        K2_STEP(au0 + (k << 9), av0 + (k << 9), aw0 + (k << 3));
    }

    // Epilogue: lo+hi + C_s + D_r + bc -> relu -> float2 stores
    const float bc = __ldg(bcat);
    const int s = s0 + 2 * lane;
    const float c0 = Cs[2 * lane] + bc;
    const float c1 = Cs[2 * lane + 1] + bc;
    if (s < R) {
        u64 accL[8] = {a00, a10, a20, a30, a40, a50, a60, a70};
        u64 accH[8] = {a01, a11, a21, a31, a41, a51, a61, a71};
        #pragma unroll
        for (int i = 0; i < 8; i++) {
            const int rec = r0 + 8 * wg + i;
            if (rec < R) {
                const float dr = Ds[8 * wg + i];
                float l0, h0, l1, h1;
                unpack2(accL[i], l0, h0);
                unpack2(accH[i], l1, h1);
                float2 o;
                o.x = fmaxf(l0 + h0 + c0 + dr, 0.0f);
                o.y = fmaxf(l1 + h1 + c1 + dr, 0.0f);
                *(float2*)&out[((size_t)(b * R + rec)) * R + s] = o;
            }
        }
    }
}

extern "C" void kernel_launch(void* const* d_in, const int* in_sizes, int n_in,
                              void* d_out, int out_size) {
    (void)in_sizes; (void)n_in; (void)out_size;
    const float* x    = (const float*)d_in[0];  // (16,360,64)
    const float* Wout = (const float*)d_in[1];  // (128,64)
    const float* bout = (const float*)d_in[2];  // (64)
    const float* Wcat = (const float*)d_in[3];  // (64,1)
    const float* bcat = (const float*)d_in[4];  // (1)
    float* out = (float*)d_out;                 // (16,360,360,1) fp32

    k1_uv<<<360, 256>>>(x, Wout, bout);                   // 5760 rows / 16
    k2_pair<<<dim3(6, 6, 16), 256>>>(Wcat, bcat, out);    // 6 send x 6 rec x 16 batch
}